// round 1
// baseline (speedup 1.0000x reference)
#include <cuda_runtime.h>

// Aggregation: out[n, g*32+wc, h, w] =
//   sum_{kh,kw} x_reflect[n, g*32+wc, h+kh-1, w+kw-1] * weight[n, wc, kh*3+kw, h, w]
//
// Shapes (fixed by the problem):
//   x      : (8, 256, 128, 128) f32
//   weight : (8, 32, 9, 128, 128) f32
//   out    : (8, 256, 128, 128) f32
//
// Strategy: memory-bound. One thread owns (n, wc, h, w..w+3) and loops over
// the G=8 groups, so the 9 weight float4s are loaded from DRAM exactly once
// and reused from registers for all 8 output channels. All main-path loads
// and the store are float4 (rows are 512B aligned, w is a multiple of 4).

namespace {
constexpr int N  = 8;
constexpr int C  = 256;
constexpr int H  = 128;
constexpr int W  = 128;
constexpr int WC = 32;
constexpr int G  = C / WC;   // 8
constexpr int HW = H * W;
}

__global__ __launch_bounds__(256, 8)
void agg_kernel(const float* __restrict__ x,
                const float* __restrict__ wt,
                float* __restrict__ out)
{
    const int tid = blockIdx.x * 256 + threadIdx.x;
    // Decode: w4 (32) fastest, then h (128), then wc (32), then n (8)
    const int w4 = tid & 31;
    const int h  = (tid >> 5) & 127;
    const int wc = (tid >> 12) & 31;
    const int n  = tid >> 17;
    const int w  = w4 << 2;

    // ---- Load 9 weight float4s once (reused across all 8 groups) ----
    const float4* wp = reinterpret_cast<const float4*>(
        wt + ((size_t)(n * WC + wc) * 9) * HW + (size_t)h * W + w);
    float4 wq[9];
    #pragma unroll
    for (int k = 0; k < 9; k++)
        wq[k] = wp[k * (HW / 4)];

    // ---- Reflect-pad index math (PAD=1: only -1 and 128 occur) ----
    const int hr0 = (h == 0)     ? 1     : h - 1;
    const int hr2 = (h == H - 1) ? H - 2 : h + 1;
    const int rows[3] = { hr0, h, hr2 };
    const int cm1 = (w == 0)       ? 1     : w - 1;   // column w-1 reflected
    const int cp4 = (w + 4 == W)   ? W - 2 : w + 4;   // column w+4 reflected

    const size_t x_n_base   = (size_t)n * C * HW;
    const size_t out_n_base = x_n_base;

    for (int g = 0; g < G; g++) {
        const int c = g * WC + wc;
        const float* xb = x + x_n_base + (size_t)c * HW;

        float a0 = 0.f, a1 = 0.f, a2 = 0.f, a3 = 0.f;

        #pragma unroll
        for (int kh = 0; kh < 3; kh++) {
            const float* xr = xb + rows[kh] * W;
            const float  v0 = __ldg(xr + cm1);
            const float4 xm = *reinterpret_cast<const float4*>(xr + w);
            const float  v5 = __ldg(xr + cp4);
            const float v1 = xm.x, v2 = xm.y, v3 = xm.z, v4 = xm.w;

            const float4 wA = wq[kh * 3 + 0];
            const float4 wB = wq[kh * 3 + 1];
            const float4 wD = wq[kh * 3 + 2];

            a0 = fmaf(v0, wA.x, fmaf(v1, wB.x, fmaf(v2, wD.x, a0)));
            a1 = fmaf(v1, wA.y, fmaf(v2, wB.y, fmaf(v3, wD.y, a1)));
            a2 = fmaf(v2, wA.z, fmaf(v3, wB.z, fmaf(v4, wD.z, a2)));
            a3 = fmaf(v3, wA.w, fmaf(v4, wB.w, fmaf(v5, wD.w, a3)));
        }

        float4 o; o.x = a0; o.y = a1; o.z = a2; o.w = a3;
        *reinterpret_cast<float4*>(out + out_n_base + (size_t)c * HW
                                   + (size_t)h * W + w) = o;
    }
}

extern "C" void kernel_launch(void* const* d_in, const int* in_sizes, int n_in,
                              void* d_out, int out_size)
{
    const float* x  = (const float*)d_in[0];
    const float* wt = (const float*)d_in[1];
    float* out      = (float*)d_out;

    // total threads = N * WC * H * (W/4) = 8*32*128*32 = 1,048,576
    const int total   = N * WC * H * (W / 4);
    const int threads = 256;
    const int blocks  = total / threads;  // 4096
    agg_kernel<<<blocks, threads>>>(x, wt, out);
}

// round 2
// speedup vs baseline: 3.8768x; 3.8768x over previous
#include <cuda_runtime.h>

// Aggregation: out[n, g*32+wc, h, w] =
//   sum_{kh,kw} x_reflect[n, g*32+wc, h+kh-1, w+kw-1] * weight[n, wc, kh*3+kw, h, w]
//
// Shapes: x (8,256,128,128) f32, weight (8,32,9,128,128) f32, out = x shape.
//
// Memory-bound. One thread owns (n, wc, h, w..w+3) and loops over the G=8
// groups so the 9 weight float4s are loaded from DRAM exactly once and kept
// in REGISTERS for all 8 output channels. R1 lesson: __launch_bounds__(256,8)
// capped regs at 32, forcing the compiler to reload the weights every group
// iteration (8x weight DRAM traffic). Use a 64-reg budget instead.

namespace {
constexpr int N  = 8;
constexpr int C  = 256;
constexpr int H  = 128;
constexpr int W  = 128;
constexpr int WC = 32;
constexpr int G  = C / WC;   // 8
constexpr int HW = H * W;
}

__global__ __launch_bounds__(256, 4)
void agg_kernel(const float* __restrict__ x,
                const float* __restrict__ wt,
                float* __restrict__ out)
{
    const int tid = blockIdx.x * 256 + threadIdx.x;
    // Decode: w4 (32) fastest, then h (128), then wc (32), then n (8)
    const int w4 = tid & 31;
    const int h  = (tid >> 5) & 127;
    const int wc = (tid >> 12) & 31;
    const int n  = tid >> 17;
    const int w  = w4 << 2;

    // ---- Load 9 weight float4s once (held in registers across all groups) ----
    const float4* wp = reinterpret_cast<const float4*>(
        wt + ((size_t)(n * WC + wc) * 9) * HW + (size_t)h * W + w);
    float4 wq[9];
    #pragma unroll
    for (int k = 0; k < 9; k++)
        wq[k] = wp[k * (HW / 4)];

    // ---- Reflect-pad index math (PAD=1: only -1 and 128 occur) ----
    const int hr0 = (h == 0)     ? 1     : h - 1;
    const int hr2 = (h == H - 1) ? H - 2 : h + 1;
    const int rows[3] = { hr0, h, hr2 };
    const int cm1 = (w == 0)       ? 1     : w - 1;   // column w-1 reflected
    const int cp4 = (w + 4 == W)   ? W - 2 : w + 4;   // column w+4 reflected

    const size_t x_n_base = (size_t)n * C * HW;
    const size_t hw_off   = (size_t)h * W + w;

    #pragma unroll
    for (int g = 0; g < G; g++) {
        const int c = g * WC + wc;
        const float* xb = x + x_n_base + (size_t)c * HW;

        float a0 = 0.f, a1 = 0.f, a2 = 0.f, a3 = 0.f;

        #pragma unroll
        for (int kh = 0; kh < 3; kh++) {
            const float* xr = xb + rows[kh] * W;
            const float  v0 = __ldg(xr + cm1);
            const float4 xm = *reinterpret_cast<const float4*>(xr + w);
            const float  v5 = __ldg(xr + cp4);
            const float v1 = xm.x, v2 = xm.y, v3 = xm.z, v4 = xm.w;

            const float4 wA = wq[kh * 3 + 0];
            const float4 wB = wq[kh * 3 + 1];
            const float4 wD = wq[kh * 3 + 2];

            a0 = fmaf(v0, wA.x, fmaf(v1, wB.x, fmaf(v2, wD.x, a0)));
            a1 = fmaf(v1, wA.y, fmaf(v2, wB.y, fmaf(v3, wD.y, a1)));
            a2 = fmaf(v2, wA.z, fmaf(v3, wB.z, fmaf(v4, wD.z, a2)));
            a3 = fmaf(v3, wA.w, fmaf(v4, wB.w, fmaf(v5, wD.w, a3)));
        }

        float4 o; o.x = a0; o.y = a1; o.z = a2; o.w = a3;
        *reinterpret_cast<float4*>(out + x_n_base + (size_t)c * HW + hw_off) = o;
    }
}

extern "C" void kernel_launch(void* const* d_in, const int* in_sizes, int n_in,
                              void* d_out, int out_size)
{
    const float* x  = (const float*)d_in[0];
    const float* wt = (const float*)d_in[1];
    float* out      = (float*)d_out;

    const int total   = N * WC * H * (W / 4);  // 1,048,576 threads
    const int threads = 256;
    const int blocks  = total / threads;       // 4096
    agg_kernel<<<blocks, threads>>>(x, wt, out);
}

// round 3
// speedup vs baseline: 4.5347x; 1.1697x over previous
#include <cuda_runtime.h>

// Aggregation: out[n, g*32+wc, h, w] =
//   sum_{kh,kw} x_reflect[n, g*32+wc, h+kh-1, w+kw-1] * weight[n, wc, kh*3+kw, h, w]
//
// x (8,256,128,128) f32, weight (8,32,9,128,128) f32, out = x shape.
//
// Traffic is at the algorithmic floor (~400MB). This revision attacks achieved
// bandwidth: R2 ncu showed L1tex at 66.5% (co-limiting DRAM at 64%) caused by
// the 2 scalar halo loads per row. A warp spans exactly one row (lane=w4), so
// halo values live in neighbor lanes: get them with warp shuffles instead of
// extra LDGs. Reflect edges are intra-lane (xm.y / xm.z).

namespace {
constexpr int N  = 8;
constexpr int C  = 256;
constexpr int H  = 128;
constexpr int W  = 128;
constexpr int WC = 32;
constexpr int G  = C / WC;   // 8
constexpr int HW = H * W;
}

__global__ __launch_bounds__(256, 4)
void agg_kernel(const float* __restrict__ x,
                const float* __restrict__ wt,
                float* __restrict__ out)
{
    const int tid = blockIdx.x * 256 + threadIdx.x;
    // Decode: w4 (32) fastest -> lane id == w4; then h (128), wc (32), n (8)
    const int w4 = tid & 31;
    const int h  = (tid >> 5) & 127;
    const int wc = (tid >> 12) & 31;
    const int n  = tid >> 17;
    const int w  = w4 << 2;

    // ---- Load 9 weight float4s once (registers, reused for all 8 groups).
    //      Read-once data: evict-first so L2 keeps x instead.
    const float4* wp = reinterpret_cast<const float4*>(
        wt + ((size_t)(n * WC + wc) * 9) * HW + (size_t)h * W + w);
    float4 wq[9];
    #pragma unroll
    for (int k = 0; k < 9; k++)
        wq[k] = __ldcs(wp + k * (HW / 4));

    // ---- Reflect rows (PAD=1: only -1 and 128 occur)
    const int hr0 = (h == 0)     ? 1     : h - 1;
    const int hr2 = (h == H - 1) ? H - 2 : h + 1;
    const int rows[3] = { hr0, h, hr2 };

    const bool lane_lo = (w4 == 0);
    const bool lane_hi = (w4 == 31);

    const size_t x_n_base = (size_t)n * C * HW;
    const size_t hw_off   = (size_t)h * W + w;

    #pragma unroll
    for (int g = 0; g < G; g++) {
        const int c = g * WC + wc;
        const float* xb = x + x_n_base + (size_t)c * HW;

        float a0 = 0.f, a1 = 0.f, a2 = 0.f, a3 = 0.f;

        #pragma unroll
        for (int kh = 0; kh < 3; kh++) {
            const float4 xm =
                *reinterpret_cast<const float4*>(xb + rows[kh] * W + w);
            const float v1 = xm.x, v2 = xm.y, v3 = xm.z, v4 = xm.w;

            // halo via warp shuffle; reflect at row ends is intra-lane
            float v0 = __shfl_up_sync(0xffffffffu, v4, 1);
            float v5 = __shfl_down_sync(0xffffffffu, v1, 1);
            if (lane_lo) v0 = v2;   // col -1 -> col 1
            if (lane_hi) v5 = v3;   // col 128 -> col 126

            const float4 wA = wq[kh * 3 + 0];
            const float4 wB = wq[kh * 3 + 1];
            const float4 wD = wq[kh * 3 + 2];

            a0 = fmaf(v0, wA.x, fmaf(v1, wB.x, fmaf(v2, wD.x, a0)));
            a1 = fmaf(v1, wA.y, fmaf(v2, wB.y, fmaf(v3, wD.y, a1)));
            a2 = fmaf(v2, wA.z, fmaf(v3, wB.z, fmaf(v4, wD.z, a2)));
            a3 = fmaf(v3, wA.w, fmaf(v4, wB.w, fmaf(v5, wD.w, a3)));
        }

        float4 o; o.x = a0; o.y = a1; o.z = a2; o.w = a3;
        // streaming store: out is write-once, keep it out of L2's way
        __stcs(reinterpret_cast<float4*>(
                   out + x_n_base + (size_t)c * HW + hw_off), o);
    }
}

extern "C" void kernel_launch(void* const* d_in, const int* in_sizes, int n_in,
                              void* d_out, int out_size)
{
    const float* x  = (const float*)d_in[0];
    const float* wt = (const float*)d_in[1];
    float* out      = (float*)d_out;

    const int total   = N * WC * H * (W / 4);  // 1,048,576 threads
    const int threads = 256;
    const int blocks  = total / threads;       // 4096
    agg_kernel<<<blocks, threads>>>(x, wt, out);
}

// round 4
// speedup vs baseline: 4.8159x; 1.0620x over previous
#include <cuda_runtime.h>

// Aggregation: out[n, g*32+wc, h, w] =
//   sum_{kh,kw} x_reflect[n, g*32+wc, h+kh-1, w+kw-1] * weight[n, wc, kh*3+kw, h, w]
//
// x (8,256,128,128) f32, weight (8,32,9,128,128) f32, out = x shape.
//
// Traffic is at the algorithmic floor; R4 attacks DRAM efficiency (72% busy).
// kh-outer restructure: 32 persistent accumulator regs, per-kh phase issues
// 8 independent x-row loads back-to-back (deep MLP batch) + 3 weight loads,
// and all 8 output stores happen as one contiguous write burst at the end.
// Halo columns come from warp shuffles (a warp spans one full row).

namespace {
constexpr int N  = 8;
constexpr int C  = 256;
constexpr int H  = 128;
constexpr int W  = 128;
constexpr int WC = 32;
constexpr int G  = C / WC;   // 8
constexpr int HW = H * W;
}

__global__ __launch_bounds__(256, 3)
void agg_kernel(const float* __restrict__ x,
                const float* __restrict__ wt,
                float* __restrict__ out)
{
    const int tid = blockIdx.x * 256 + threadIdx.x;
    // Decode: w4 (32) fastest -> lane id == w4; then h (128), wc (32), n (8)
    const int w4 = tid & 31;
    const int h  = (tid >> 5) & 127;
    const int wc = (tid >> 12) & 31;
    const int n  = tid >> 17;
    const int w  = w4 << 2;

    // Reflect rows (PAD=1: only -1 and 128 occur)
    const int hr0 = (h == 0)     ? 1     : h - 1;
    const int hr2 = (h == H - 1) ? H - 2 : h + 1;
    const int rows[3] = { hr0, h, hr2 };

    const bool lane_lo = (w4 == 0);
    const bool lane_hi = (w4 == 31);

    const size_t x_n_base = (size_t)n * C * HW;
    // x base for group 0's channel (= wc) at column w; per-group offset is
    // a compile-time constant 32*HW elements (fits LDG immediate offsets).
    const float* xbase = x + x_n_base + (size_t)wc * HW + w;

    const float4* wp = reinterpret_cast<const float4*>(
        wt + ((size_t)(n * WC + wc) * 9) * HW + (size_t)h * W + w);

    float4 acc[G];
    #pragma unroll
    for (int g = 0; g < G; g++)
        acc[g] = make_float4(0.f, 0.f, 0.f, 0.f);

    #pragma unroll
    for (int kh = 0; kh < 3; kh++) {
        // 3 weight float4s for this kh (read-once: evict-first)
        const float4 wA = __ldcs(wp + (kh * 3 + 0) * (HW / 4));
        const float4 wB = __ldcs(wp + (kh * 3 + 1) * (HW / 4));
        const float4 wD = __ldcs(wp + (kh * 3 + 2) * (HW / 4));

        // 8 independent x-row loads, batched back-to-back
        const float* xr = xbase + rows[kh] * W;
        float4 xm[G];
        #pragma unroll
        for (int g = 0; g < G; g++)
            xm[g] = *reinterpret_cast<const float4*>(xr + g * (WC * HW));

        #pragma unroll
        for (int g = 0; g < G; g++) {
            const float v1 = xm[g].x, v2 = xm[g].y,
                        v3 = xm[g].z, v4 = xm[g].w;
            // halo via warp shuffle; reflect at row ends is intra-lane
            float v0 = __shfl_up_sync(0xffffffffu, v4, 1);
            float v5 = __shfl_down_sync(0xffffffffu, v1, 1);
            if (lane_lo) v0 = v2;   // col -1  -> col 1
            if (lane_hi) v5 = v3;   // col 128 -> col 126

            acc[g].x = fmaf(v0, wA.x, fmaf(v1, wB.x, fmaf(v2, wD.x, acc[g].x)));
            acc[g].y = fmaf(v1, wA.y, fmaf(v2, wB.y, fmaf(v3, wD.y, acc[g].y)));
            acc[g].z = fmaf(v2, wA.z, fmaf(v3, wB.z, fmaf(v4, wD.z, acc[g].z)));
            acc[g].w = fmaf(v3, wA.w, fmaf(v4, wB.w, fmaf(v5, wD.w, acc[g].w)));
        }
    }

    // One contiguous write burst: 8 streaming float4 stores
    float* ob = out + x_n_base + (size_t)wc * HW + (size_t)h * W + w;
    #pragma unroll
    for (int g = 0; g < G; g++)
        __stcs(reinterpret_cast<float4*>(ob + g * (WC * HW)), acc[g]);
}

extern "C" void kernel_launch(void* const* d_in, const int* in_sizes, int n_in,
                              void* d_out, int out_size)
{
    const float* x  = (const float*)d_in[0];
    const float* wt = (const float*)d_in[1];
    float* out      = (float*)d_out;

    const int total   = N * WC * H * (W / 4);  // 1,048,576 threads
    const int threads = 256;
    const int blocks  = total / threads;       // 4096
    agg_kernel<<<blocks, threads>>>(x, wt, out);
}